// round 14
// baseline (speedup 1.0000x reference)
#include <cuda_runtime.h>

#define NQ 100
#define HH 640
#define WW 640
#define HWPX (HH*WW)
#define WORDS (HWPX/32)
#define VWORDS (WORDS/4)
#define FH 40
#define FW 40
#define FHW (FH*FW)
#define DD 384
#define MAXB 2
#define MAXPAIRS 4950
#define PGRID 512
#define SLAB 16
#define SROWP 656
#define PKCH 16
#define MASK_T 0.4f
#define SCORE_T 0.35f
#define IOU_T 0.85f
#define TOPK 40

// ---------------- scratch (device globals; no allocation allowed) ----------------
__device__ int      g_order[MAXB][NQ];
__device__ float    g_ss[MAXB][NQ];
__device__ int      g_sl[MAXB][NQ];
__device__ unsigned char g_need[MAXB][NQ];
__device__ unsigned short g_pairs[MAXB][MAXPAIRS];
__device__ int      g_npairs[MAXB];
__device__ unsigned g_bits[MAXB][NQ][WORDS];
__device__ int      g_area[MAXB][NQ];
__device__ unsigned g_conf[MAXB][NQ][4];
__device__ int      g_done[MAXB];
__device__ int      g_qdone[MAXB][NQ];
__device__ int      g_count[MAXB];
__device__ int      g_src[MAXB][NQ];
__device__ int      g_hasbb[MAXB][NQ];
__device__ float    g_fs[MAXB][NQ];
__device__ int      g_fl[MAXB][NQ];
__device__ int      g_sx1[MAXB][NQ], g_sx2[MAXB][NQ], g_sy1[MAXB][NQ], g_sy2[MAXB][NQ];
__device__ int      g_x1[MAXB][NQ], g_x2[MAXB][NQ], g_y1[MAXB][NQ], g_y2[MAXB][NQ];
__device__ float    g_tmp[MAXB][NQ][HH][FW];
__device__ float    g_ms[MAXB][NQ][FHW];
__device__ float    g_pool[MAXB][NQ][DD];
__device__ float    g_invn[FW];

__device__ __forceinline__ float logitf_(float p) {
    p = fminf(fmaxf(p, 1e-4f), 1.0f - 1e-4f);
    return 0.69314718056f * (__log2f(p) - __log2f(1.0f - p));
}

// ---------------- sort + pair enumeration + all scratch init ---------------------
__global__ void k_sortinit(const float* __restrict__ scores, const int* __restrict__ labels) {
    int b = blockIdx.x, tid = threadIdx.x;
    __shared__ float s[NQ];
    __shared__ int l[NQ];
    __shared__ float ss_s[NQ];
    __shared__ int sl_s[NQ];
    __shared__ unsigned char need[NQ];
    __shared__ int np;
    if (tid < NQ) { s[tid] = scores[b * NQ + tid]; l[tid] = labels[b * NQ + tid]; need[tid] = 0; }
    if (tid == 0) { np = 0; g_done[b] = 0; }
    for (int i = tid; i < NQ * DD; i += 128) (&g_pool[b][0][0])[i] = 0.f;
    if (tid < NQ) {
        g_area[b][tid] = 0;
        g_qdone[b][tid] = 0;
        g_x1[b][tid] = 1 << 29; g_x2[b][tid] = -1;
        g_y1[b][tid] = 1 << 29; g_y2[b][tid] = -1;
        g_sx1[b][tid] = 1 << 29; g_sx2[b][tid] = -1;
        g_sy1[b][tid] = 1 << 29; g_sy2[b][tid] = -1;
        g_conf[b][tid][0] = 0u; g_conf[b][tid][1] = 0u;
        g_conf[b][tid][2] = 0u; g_conf[b][tid][3] = 0u;
    }
    if (tid < FW) {
        float c = 16.f * tid + 7.5f;
        int lo = max(0, 16 * tid - 8), hi = min(WW - 1, 16 * tid + 23);
        float sum = 0.f;
        for (int j = lo; j <= hi; j++) sum += 1.f - fabsf((float)j - c) * 0.0625f;
        g_invn[tid] = 1.f / sum;
    }
    __syncthreads();
    if (tid < NQ) {
        float si = s[tid];
        int r = 0;
        for (int j = 0; j < NQ; j++)
            r += (s[j] > si) || (s[j] == si && j < tid);
        g_order[b][r] = tid;
        g_ss[b][r] = si;
        g_sl[b][r] = l[tid];
        ss_s[r] = si;
        sl_s[r] = l[tid];
    }
    __syncthreads();
    if (tid < NQ && ss_s[tid] >= SCORE_T) {
        int i = tid, li = sl_s[i];
        for (int j = i + 1; j < NQ; j++)
            if (sl_s[j] == li && ss_s[j] >= SCORE_T) {
                int p = atomicAdd(&np, 1);
                g_pairs[b][p] = (unsigned short)((i << 8) | j);
                need[i] = 1; need[j] = 1;
            }
    }
    __syncthreads();
    if (tid < NQ) g_need[b][tid] = need[tid];
    if (tid == 0) g_npairs[b] = np;
}

// ---------------- pure bit-pack + area + bbox for need rows ----------------------
__global__ void k_pack(const float* __restrict__ masks) {
    int b = blockIdx.z, q = blockIdx.y, tid = threadIdx.x;
    if (!g_need[b][q]) return;
    int src = g_order[b][q];
    const float4* m4 = (const float4*)(masks + (size_t)(b * NQ + src) * HWPX);
    int warp = tid >> 5, lane = tid & 31;
    int wb = blockIdx.x * 320 + warp * 40;
    int acc = 0;
    int mnx = WW, mxx = -1, mny = 1 << 29, mxy = -1;
#pragma unroll
    for (int i = 0; i < 10; i++) {
        int wd = wb + i * 4;
        int f = wd * 8 + lane;
        float4 m = __ldcs(&m4[f]);
        bool a0 = m.x > MASK_T, a1 = m.y > MASK_T, a2 = m.z > MASK_T, a3 = m.w > MASK_T;
        unsigned b0 = __ballot_sync(0xffffffffu, a0);
        unsigned b1 = __ballot_sync(0xffffffffu, a1);
        unsigned b2 = __ballot_sync(0xffffffffu, a2);
        unsigned b3 = __ballot_sync(0xffffffffu, a3);
        if (lane == 0) {
            *(uint4*)&g_bits[b][q][wd] = make_uint4(b0, b1, b2, b3);
            acc += __popc(b0) + __popc(b1) + __popc(b2) + __popc(b3);
        }
        if (a0 | a1 | a2 | a3) {
            int r = f / 160;
            int xb = 4 * (f - r * 160);
            int x0 = xb + (a0 ? 0 : (a1 ? 1 : (a2 ? 2 : 3)));
            int x1 = xb + (a3 ? 3 : (a2 ? 2 : (a1 ? 1 : 0)));
            mnx = min(mnx, x0); mxx = max(mxx, x1);
            mny = min(mny, r);  mxy = max(mxy, r);
        }
    }
    if (lane == 0) atomicAdd(&g_area[b][q], acc);
    mnx = __reduce_min_sync(0xffffffffu, mnx);
    mxx = __reduce_max_sync(0xffffffffu, mxx);
    mny = __reduce_min_sync(0xffffffffu, mny);
    mxy = __reduce_max_sync(0xffffffffu, mxy);
    if (lane == 0 && mxy >= 0) {
        atomicMin(&g_sx1[b][q], mnx);
        atomicMax(&g_sx2[b][q], mxx);
        atomicMin(&g_sy1[b][q], mny);
        atomicMax(&g_sy2[b][q], mxy);
    }
}

// ---------------- SIDE STREAM: -20 fill of rows 40..99 (overlaps iou/main40) -----
__global__ void k_fill60(float* __restrict__ outM) {
    int b = blockIdx.z, q = 40 + blockIdx.y;
    int h0 = blockIdx.x * SLAB;
    int tid = threadIdx.x;
    float4* o4 = (float4*)(outM + ((size_t)(b * NQ + q) * HH + h0) * WW);
    float4 v = make_float4(-20.f, -20.f, -20.f, -20.f);
#pragma unroll
    for (int i = 0; i < 10; i++)
        __stcs(&o4[i * 256 + tid], v);
}

// ---------------- wide-grid IoU; last block runs greedy + pack -------------------
__global__ void k_iou() {
    int b = blockIdx.y, tid = threadIdx.x;
    int np = g_npairs[b];
    __shared__ float red[8];
    for (int p = blockIdx.x; p < np; p += PGRID) {
        int pr = g_pairs[b][p];
        int i = pr >> 8, j = pr & 255;
        const uint4* bi = (const uint4*)g_bits[b][i];
        const uint4* bj = (const uint4*)g_bits[b][j];
        int acc = 0;
        for (int wd = tid; wd < VWORDS; wd += 256) {
            uint4 a = bi[wd], c = bj[wd];
            acc += __popc(a.x & c.x) + __popc(a.y & c.y) +
                   __popc(a.z & c.z) + __popc(a.w & c.w);
        }
        acc = __reduce_add_sync(0xffffffffu, acc);
        if ((tid & 31) == 0) red[tid >> 5] = (float)acc;
        __syncthreads();
        if (tid == 0) {
            float inter = red[0] + red[1] + red[2] + red[3] +
                          red[4] + red[5] + red[6] + red[7];
            float uni = fmaxf((float)(g_area[b][i] + g_area[b][j]) - inter, 1.f);
            if (inter / uni >= IOU_T) atomicOr(&g_conf[b][j][i >> 5], 1u << (i & 31));
        }
        __syncthreads();
    }
    __shared__ int is_last;
    if (tid == 0) {
        __threadfence();
        is_last = (atomicAdd(&g_done[b], 1) == PGRID - 1) ? 1 : 0;
    }
    __syncthreads();
    if (!is_last) return;
    __threadfence();
    __shared__ unsigned conf[NQ][4];
    __shared__ float ssc[NQ];
    __shared__ unsigned keptm[4];
    __shared__ int s_count;
    if (tid < NQ) {
        conf[tid][0] = g_conf[b][tid][0];
        conf[tid][1] = g_conf[b][tid][1];
        conf[tid][2] = g_conf[b][tid][2];
        conf[tid][3] = g_conf[b][tid][3];
        ssc[tid] = g_ss[b][tid];
    }
    __syncthreads();
    if (tid == 0) {
        unsigned k0 = 0, k1 = 0, k2 = 0, k3 = 0;
        int count = 0;
        bool stopped = false;
        for (int i = 0; i < NQ; i++) {
            if (ssc[i] < SCORE_T) stopped = true;
            unsigned c = (k0 & conf[i][0]) | (k1 & conf[i][1]) |
                         (k2 & conf[i][2]) | (k3 & conf[i][3]);
            bool take = !stopped && (c == 0u);
            if (take) {
                unsigned bit = 1u << (i & 31);
                if (i < 32) k0 |= bit; else if (i < 64) k1 |= bit;
                else if (i < 96) k2 |= bit; else k3 |= bit;
                count++;
                if (count >= TOPK) stopped = true;
            }
        }
        keptm[0] = k0; keptm[1] = k1; keptm[2] = k2; keptm[3] = k3;
        s_count = count;
        g_count[b] = count;
    }
    __syncthreads();
    if (tid < NQ) {
        int w = tid >> 5, bb = tid & 31;
        bool kept = (keptm[w] >> bb) & 1u;
        int below = __popc(keptm[w] & ((bb == 0) ? 0u : ((1u << bb) - 1u)));
        for (int ww = 0; ww < w; ww++) below += __popc(keptm[ww]);
        int dst = kept ? below : (s_count + (tid - below));
        g_src[b][dst] = g_order[b][tid];
        g_fs[b][dst] = ssc[tid];
        g_fl[b][dst] = g_sl[b][tid];
        int hb = g_need[b][tid] ? 1 : 0;
        g_hasbb[b][dst] = hb;
        if (hb) {
            g_x1[b][dst] = g_sx1[b][tid];
            g_x2[b][dst] = g_sx2[b][tid];
            g_y1[b][dst] = g_sy1[b][tid];
            g_y2[b][dst] = g_sy2[b][tid];
        }
    }
}

// ---------------- rows 0..39: logits + bbox + W-downsample; last slab: H-reduce --
__global__ void k_main40(const float* __restrict__ masks, float* __restrict__ outM) {
    int b = blockIdx.z, q = blockIdx.y;
    int h0 = blockIdx.x * SLAB;
    int tid = threadIdx.x;
    float4* o4 = (float4*)(outM + ((size_t)(b * NQ + q) * HH + h0) * WW);
    if (q >= g_count[b]) {
        float4 v = make_float4(-20.f, -20.f, -20.f, -20.f);
#pragma unroll
        for (int i = 0; i < 10; i++)
            __stcs(&o4[i * 256 + tid], v);
        return;
    }
    int src = g_src[b][q];
    const float4* m4 = (const float4*)(masks + ((size_t)(b * NQ + src) * HH + h0) * WW);
    __shared__ float srow[SLAB * SROWP];
    __shared__ int rmn[8], rmx[8], rmy0[8], rmy1[8];
    int warp = tid >> 5, lane = tid & 31;
    {
        int r = tid >> 4, e = tid & 15;
        srow[r * SROWP + (e < 8 ? e : 640 + e)] = 0.f;
    }
    bool dobb = !g_hasbb[b][q];
    if (dobb) {
        int mnx = WW, mxx = -1, mny = 1 << 29, mxy = -1;
#pragma unroll
        for (int i = 0; i < 10; i++) {
            int idx = i * 256 + tid;
            int r = idx / 160, c = idx - r * 160;
            float4 m = __ldcs(&m4[idx]);
            float p0 = __saturatef(m.x), p1 = __saturatef(m.y);
            float p2 = __saturatef(m.z), p3 = __saturatef(m.w);
            *(float4*)&srow[r * SROWP + 8 + 4 * c] = make_float4(p0, p1, p2, p3);
            float4 o;
            o.x = logitf_(p0); o.y = logitf_(p1); o.z = logitf_(p2); o.w = logitf_(p3);
            __stcs(&o4[idx], o);
            bool a0 = m.x > MASK_T, a1 = m.y > MASK_T, a2 = m.z > MASK_T, a3 = m.w > MASK_T;
            if (a0 | a1 | a2 | a3) {
                int xb = 4 * c;
                int x0 = xb + (a0 ? 0 : (a1 ? 1 : (a2 ? 2 : 3)));
                int x1 = xb + (a3 ? 3 : (a2 ? 2 : (a1 ? 1 : 0)));
                mnx = min(mnx, x0); mxx = max(mxx, x1);
                mny = min(mny, r);  mxy = max(mxy, r);
            }
        }
        mnx = __reduce_min_sync(0xffffffffu, mnx);
        mxx = __reduce_max_sync(0xffffffffu, mxx);
        mny = __reduce_min_sync(0xffffffffu, mny);
        mxy = __reduce_max_sync(0xffffffffu, mxy);
        if (lane == 0) { rmn[warp] = mnx; rmx[warp] = mxx; rmy0[warp] = mny; rmy1[warp] = mxy; }
    } else {
#pragma unroll
        for (int i = 0; i < 10; i++) {
            int idx = i * 256 + tid;
            int r = idx / 160, c = idx - r * 160;
            float4 m = __ldcs(&m4[idx]);
            float p0 = __saturatef(m.x), p1 = __saturatef(m.y);
            float p2 = __saturatef(m.z), p3 = __saturatef(m.w);
            *(float4*)&srow[r * SROWP + 8 + 4 * c] = make_float4(p0, p1, p2, p3);
            float4 o;
            o.x = logitf_(p0); o.y = logitf_(p1); o.z = logitf_(p2); o.w = logitf_(p3);
            __stcs(&o4[idx], o);
        }
    }
    __syncthreads();
    if (dobb && tid == 0) {
        int a = rmn[0], c = rmx[0], y0 = rmy0[0], y1 = rmy1[0];
        for (int w = 1; w < 8; w++) {
            a = min(a, rmn[w]); c = max(c, rmx[w]);
            y0 = min(y0, rmy0[w]); y1 = max(y1, rmy1[w]);
        }
        if (c >= 0) {
            atomicMin(&g_x1[b][q], a);
            atomicMax(&g_x2[b][q], c);
            atomicMin(&g_y1[b][q], h0 + y0);
            atomicMax(&g_y2[b][q], h0 + y1);
        }
    }
    int half = lane >> 4, hl = lane & 15;
    float w0 = 1.f - fabsf((float)hl - 15.5f) * 0.0625f;
    float w1 = 1.f - ((float)hl + 0.5f) * 0.0625f;
    for (int pr = warp; pr < (SLAB * FW) / 2; pr += 8) {
        int o = pr * 2 + half;
        int r = o / FW, wo = o - r * FW;
        const float* rp = srow + r * SROWP + 16 * wo;
        float acc = rp[hl] * w0 + rp[hl + 16] * w1;
        acc += __shfl_xor_sync(0xffffffffu, acc, 8);
        acc += __shfl_xor_sync(0xffffffffu, acc, 4);
        acc += __shfl_xor_sync(0xffffffffu, acc, 2);
        acc += __shfl_xor_sync(0xffffffffu, acc, 1);
        if (hl == 0)
            g_tmp[b][q][h0 + r][wo] = acc * g_invn[wo];
    }
    // last-finishing slab for this (b,q) does the H-reduce from L2-hot g_tmp
    __shared__ int lastq;
    if (tid == 0) {
        __threadfence();
        lastq = (atomicAdd(&g_qdone[b][q], 1) == (HH / SLAB) - 1) ? 1 : 0;
    }
    __syncthreads();
    if (!lastq) return;
    __threadfence();
    for (int idx = tid; idx < FHW; idx += 256) {
        int ho = idx / FW, wo = idx - ho * FW;
        float c = 16.f * ho + 7.5f;
        int lo = max(0, 16 * ho - 8), hi = min(HH - 1, 16 * ho + 23);
        float acc = 0.f;
#pragma unroll 8
        for (int h = lo; h <= hi; h++)
            acc += (1.f - fabsf((float)h - c) * 0.0625f) * g_tmp[b][q][h][wo];
        g_ms[b][q][idx] = acc * g_invn[ho];
    }
}

// ---------------- pooled = mask_small @ feat^T (coalesced smem-tiled) ------------
__global__ void k_pool(const float* __restrict__ feat) {
    int b = blockIdx.z;
    int q0 = blockIdx.y * 10;
    int hw0 = blockIdx.x * 320;
    int count = g_count[b];
    int tid = threadIdx.x;
    int warp = tid >> 5, lane = tid & 31;
    __shared__ float ms[10][320];
    __shared__ float ft[DD][PKCH + 1];
    for (int i = tid; i < 3200; i += 384) {
        int qq = i / 320, k = i - qq * 320;
        int q = q0 + qq;
        ms[qq][k] = (q < count) ? g_ms[b][q][hw0 + k] : 0.f;
    }
    float acc[10];
#pragma unroll
    for (int i = 0; i < 10; i++) acc[i] = 0.f;
    const float* fb = feat + (size_t)b * DD * FHW + hw0;
    int rbase = warp * 32 + (lane >> 4);
    int kk = lane & 15;
    for (int k0 = 0; k0 < 320; k0 += PKCH) {
        __syncthreads();
#pragma unroll
        for (int rr = 0; rr < 16; rr++) {
            int d = rbase + rr * 2;
            ft[d][kk] = __ldg(&fb[(size_t)d * FHW + k0 + kk]);
        }
        __syncthreads();
#pragma unroll
        for (int k = 0; k < PKCH; k++) {
            float fv = ft[tid][k];
#pragma unroll
            for (int qq = 0; qq < 10; qq++) acc[qq] += ms[qq][k0 + k] * fv;
        }
    }
#pragma unroll
    for (int qq = 0; qq < 10; qq++)
        if (q0 + qq < count) atomicAdd(&g_pool[b][q0 + qq][tid], acc[qq]);
}

// ---------------- finalize --------------------------------------------------------
__global__ void k_final(float* __restrict__ outCls, float* __restrict__ outBox,
                        float* __restrict__ outEmb, int C1, int Cm1) {
    int b = blockIdx.y, q = blockIdx.x, tid = threadIdx.x;
    int count = g_count[b];
    bool valid = q < count;
    int label = min(max(g_fl[b][q], 0), Cm1);
    float slog = logitf_(fminf(fmaxf(g_fs[b][q], 0.f), 1.f));
    for (int c = tid; c < C1; c += blockDim.x) {
        float v = -10.f;
        if (valid) {
            if (c == C1 - 1) v = 0.f;
            if (c == label) v = slog;
        }
        outCls[(size_t)(b * NQ + q) * C1 + c] = v;
    }
    if (tid == 0) {
        float b0 = 0.f, b1 = 0.f, b2 = 0.f, b3 = 0.f;
        if (valid && g_y2[b][q] >= 0) {
            float x1 = (float)g_x1[b][q], x2 = (float)g_x2[b][q];
            float y1 = (float)g_y1[b][q], y2 = (float)g_y2[b][q];
            b0 = fminf(fmaxf((x1 + x2) * 0.5f / (float)WW, 0.f), 1.f);
            b1 = fminf(fmaxf((y1 + y2) * 0.5f / (float)HH, 0.f), 1.f);
            b2 = fminf(fmaxf(fmaxf(x2 - x1, 0.f) / (float)WW, 0.f), 1.f);
            b3 = fminf(fmaxf(fmaxf(y2 - y1, 0.f) / (float)HH, 0.f), 1.f);
        }
        float4* bp = (float4*)(outBox + (size_t)(b * NQ + q) * 4);
        *bp = make_float4(b0, b1, b2, b3);
    }
    __shared__ float sh[12];
    __shared__ float s_den, s_nrm;
    float part = 0.f;
    if (valid)
        for (int i = tid; i < FHW; i += blockDim.x) part += g_ms[b][q][i];
    for (int o = 16; o > 0; o >>= 1) part += __shfl_down_sync(0xffffffffu, part, o);
    if ((tid & 31) == 0) sh[tid >> 5] = part;
    __syncthreads();
    if (tid == 0) {
        float s = 0.f;
        for (int i = 0; i < 12; i++) s += sh[i];
        s_den = fmaxf(s, 1e-6f);
    }
    __syncthreads();
    float v = valid ? g_pool[b][q][tid] / s_den : 0.f;
    float p2 = v * v;
    for (int o = 16; o > 0; o >>= 1) p2 += __shfl_down_sync(0xffffffffu, p2, o);
    if ((tid & 31) == 0) sh[tid >> 5] = p2;
    __syncthreads();
    if (tid == 0) {
        float s = 0.f;
        for (int i = 0; i < 12; i++) s += sh[i];
        s_nrm = fmaxf(sqrtf(s), 1e-12f);
    }
    __syncthreads();
    outEmb[(size_t)(b * NQ + q) * DD + tid] = valid ? v / s_nrm : 0.f;
}

// ---------------- launch ----------------------------------------------------------
extern "C" void kernel_launch(void* const* d_in, const int* in_sizes, int n_in,
                              void* d_out, int out_size) {
    const float* masks  = (const float*)d_in[0];
    const int*   labels = (const int*)d_in[1];
    const float* scores = (const float*)d_in[2];
    const float* feat   = (const float*)d_in[3];
    float* out = (float*)d_out;

    int B = in_sizes[2] / NQ;
    if (B < 1) B = 1;
    if (B > MAXB) B = MAXB;
    long long fixed = (long long)B * NQ * HWPX + (long long)B * NQ * 4 + (long long)B * NQ * DD;
    int C1 = (int)(((long long)out_size - fixed) / ((long long)B * NQ));
    if (C1 < 2) C1 = 81;

    size_t off1 = (size_t)B * NQ * HWPX;
    size_t off2 = off1 + (size_t)B * NQ * C1;
    size_t off3 = off2 + (size_t)B * NQ * 4;

    static cudaStream_t s2 = nullptr;
    static cudaEvent_t evFork = nullptr, evJoin = nullptr;
    if (s2 == nullptr) {
        cudaStreamCreateWithFlags(&s2, cudaStreamNonBlocking);
        cudaEventCreateWithFlags(&evFork, cudaEventDisableTiming);
        cudaEventCreateWithFlags(&evJoin, cudaEventDisableTiming);
    }

    k_sortinit<<<B, 128>>>(scores, labels);
    k_pack<<<dim3(40, NQ, B), 256>>>(masks);

    // fork AFTER pack: fill runs during iou's DRAM-idle window + main40
    cudaEventRecord(evFork, 0);
    cudaStreamWaitEvent(s2, evFork, 0);
    k_fill60<<<dim3(HH / SLAB, 60, B), 256, 0, s2>>>(out);

    k_iou<<<dim3(PGRID, B), 256>>>();
    k_main40<<<dim3(HH / SLAB, TOPK, B), 256>>>(masks, out);   // includes H-reduce
    k_pool<<<dim3(5, 4, B), 384>>>(feat);
    k_final<<<dim3(NQ, B), 384>>>(out + off1, out + off2, out + off3, C1, C1 - 2);

    cudaEventRecord(evJoin, s2);
    cudaStreamWaitEvent(0, evJoin, 0);
}

// round 15
// speedup vs baseline: 1.0987x; 1.0987x over previous
#include <cuda_runtime.h>

#define NQ 100
#define HH 640
#define WW 640
#define HWPX (HH*WW)
#define WORDS (HWPX/32)
#define VWORDS (WORDS/4)
#define FH 40
#define FW 40
#define FHW (FH*FW)
#define DD 384
#define MAXB 2
#define MAXPAIRS 4950
#define PGRID 512
#define SLAB 16
#define MSLAB 8
#define SROWP 656
#define PKCH 16
#define MASK_T 0.4f
#define SCORE_T 0.35f
#define IOU_T 0.85f
#define TOPK 40

// ---------------- scratch (device globals; no allocation allowed) ----------------
__device__ int      g_order[MAXB][NQ];
__device__ float    g_ss[MAXB][NQ];
__device__ int      g_sl[MAXB][NQ];
__device__ unsigned char g_need[MAXB][NQ];
__device__ unsigned short g_pairs[MAXB][MAXPAIRS];
__device__ int      g_npairs[MAXB];
__device__ unsigned g_bits[MAXB][NQ][WORDS];
__device__ int      g_area[MAXB][NQ];
__device__ unsigned g_conf[MAXB][NQ][4];
__device__ int      g_done[MAXB];
__device__ int      g_count[MAXB];
__device__ int      g_src[MAXB][NQ];
__device__ int      g_hasbb[MAXB][NQ];
__device__ float    g_fs[MAXB][NQ];
__device__ int      g_fl[MAXB][NQ];
__device__ int      g_sx1[MAXB][NQ], g_sx2[MAXB][NQ], g_sy1[MAXB][NQ], g_sy2[MAXB][NQ];
__device__ int      g_x1[MAXB][NQ], g_x2[MAXB][NQ], g_y1[MAXB][NQ], g_y2[MAXB][NQ];
__device__ float    g_tmp[MAXB][NQ][HH][FW];
__device__ float    g_ms[MAXB][NQ][FHW];
__device__ float    g_pool[MAXB][NQ][DD];
__device__ float    g_invn[FW];

__device__ __forceinline__ float logitf_(float p) {
    p = fminf(fmaxf(p, 1e-4f), 1.0f - 1e-4f);
    return 0.69314718056f * (__log2f(p) - __log2f(1.0f - p));
}

// ---------------- launch 1: sort + pair enumeration + all scratch init -----------
__global__ void k_sortinit(const float* __restrict__ scores, const int* __restrict__ labels) {
    int b = blockIdx.x, tid = threadIdx.x;
    __shared__ float s[NQ];
    __shared__ int l[NQ];
    __shared__ float ss_s[NQ];
    __shared__ int sl_s[NQ];
    __shared__ unsigned char need[NQ];
    __shared__ int np;
    if (tid < NQ) { s[tid] = scores[b * NQ + tid]; l[tid] = labels[b * NQ + tid]; need[tid] = 0; }
    if (tid == 0) { np = 0; g_done[b] = 0; }
    for (int i = tid; i < NQ * DD; i += 128) (&g_pool[b][0][0])[i] = 0.f;
    if (tid < NQ) {
        g_area[b][tid] = 0;
        g_x1[b][tid] = 1 << 29; g_x2[b][tid] = -1;
        g_y1[b][tid] = 1 << 29; g_y2[b][tid] = -1;
        g_sx1[b][tid] = 1 << 29; g_sx2[b][tid] = -1;
        g_sy1[b][tid] = 1 << 29; g_sy2[b][tid] = -1;
        g_conf[b][tid][0] = 0u; g_conf[b][tid][1] = 0u;
        g_conf[b][tid][2] = 0u; g_conf[b][tid][3] = 0u;
    }
    if (tid < FW) {
        float c = 16.f * tid + 7.5f;
        int lo = max(0, 16 * tid - 8), hi = min(WW - 1, 16 * tid + 23);
        float sum = 0.f;
        for (int j = lo; j <= hi; j++) sum += 1.f - fabsf((float)j - c) * 0.0625f;
        g_invn[tid] = 1.f / sum;
    }
    __syncthreads();
    if (tid < NQ) {
        float si = s[tid];
        int r = 0;
        for (int j = 0; j < NQ; j++)
            r += (s[j] > si) || (s[j] == si && j < tid);
        g_order[b][r] = tid;
        g_ss[b][r] = si;
        g_sl[b][r] = l[tid];
        ss_s[r] = si;
        sl_s[r] = l[tid];
    }
    __syncthreads();
    if (tid < NQ && ss_s[tid] >= SCORE_T) {
        int i = tid, li = sl_s[i];
        for (int j = i + 1; j < NQ; j++)
            if (sl_s[j] == li && ss_s[j] >= SCORE_T) {
                int p = atomicAdd(&np, 1);
                g_pairs[b][p] = (unsigned short)((i << 8) | j);
                need[i] = 1; need[j] = 1;
            }
    }
    __syncthreads();
    if (tid < NQ) g_need[b][tid] = need[tid];
    if (tid == 0) g_npairs[b] = np;
}

// ---------------- launch 2: fill rows 40..99 + bit-pack + area + bbox ------------
__global__ void k_packfill(const float* __restrict__ masks, float* __restrict__ outM) {
    int b = blockIdx.z, y = blockIdx.y, tid = threadIdx.x;
    if (y >= NQ) {
        int q = y - 60;                        // rows 40..99: always invalid
        int h0 = blockIdx.x * SLAB;
        float4* o4 = (float4*)(outM + ((size_t)(b * NQ + q) * HH + h0) * WW);
        float4 v = make_float4(-20.f, -20.f, -20.f, -20.f);
#pragma unroll
        for (int i = 0; i < 10; i++)
            __stcs(&o4[i * 256 + tid], v);
        return;
    }
    int q = y;
    if (!g_need[b][q]) return;
    int src = g_order[b][q];
    const float4* m4 = (const float4*)(masks + (size_t)(b * NQ + src) * HWPX);
    int warp = tid >> 5, lane = tid & 31;
    int wb = blockIdx.x * 320 + warp * 40;     // 40 blocks * 8 warps * 40 words
    int acc = 0;
    int mnx = WW, mxx = -1, mny = 1 << 29, mxy = -1;
#pragma unroll
    for (int i = 0; i < 10; i++) {
        int wd = wb + i * 4;
        int f = wd * 8 + lane;
        float4 m = __ldcs(&m4[f]);
        bool a0 = m.x > MASK_T, a1 = m.y > MASK_T, a2 = m.z > MASK_T, a3 = m.w > MASK_T;
        unsigned b0 = __ballot_sync(0xffffffffu, a0);
        unsigned b1 = __ballot_sync(0xffffffffu, a1);
        unsigned b2 = __ballot_sync(0xffffffffu, a2);
        unsigned b3 = __ballot_sync(0xffffffffu, a3);
        if (lane == 0) {
            *(uint4*)&g_bits[b][q][wd] = make_uint4(b0, b1, b2, b3);
            acc += __popc(b0) + __popc(b1) + __popc(b2) + __popc(b3);
        }
        if (a0 | a1 | a2 | a3) {
            int r = f / 160;
            int xb = 4 * (f - r * 160);
            int x0 = xb + (a0 ? 0 : (a1 ? 1 : (a2 ? 2 : 3)));
            int x1 = xb + (a3 ? 3 : (a2 ? 2 : (a1 ? 1 : 0)));
            mnx = min(mnx, x0); mxx = max(mxx, x1);
            mny = min(mny, r);  mxy = max(mxy, r);
        }
    }
    if (lane == 0) atomicAdd(&g_area[b][q], acc);
    mnx = __reduce_min_sync(0xffffffffu, mnx);
    mxx = __reduce_max_sync(0xffffffffu, mxx);
    mny = __reduce_min_sync(0xffffffffu, mny);
    mxy = __reduce_max_sync(0xffffffffu, mxy);
    if (lane == 0 && mxy >= 0) {
        atomicMin(&g_sx1[b][q], mnx);
        atomicMax(&g_sx2[b][q], mxx);
        atomicMin(&g_sy1[b][q], mny);
        atomicMax(&g_sy2[b][q], mxy);
    }
}

// ---------------- launch 3: wide-grid IoU; last block runs greedy + pack ---------
__global__ void k_iou() {
    int b = blockIdx.y, tid = threadIdx.x;
    int np = g_npairs[b];
    __shared__ float red[8];
    for (int p = blockIdx.x; p < np; p += PGRID) {
        int pr = g_pairs[b][p];
        int i = pr >> 8, j = pr & 255;
        const uint4* bi = (const uint4*)g_bits[b][i];
        const uint4* bj = (const uint4*)g_bits[b][j];
        int acc = 0;
        for (int wd = tid; wd < VWORDS; wd += 256) {
            uint4 a = bi[wd], c = bj[wd];
            acc += __popc(a.x & c.x) + __popc(a.y & c.y) +
                   __popc(a.z & c.z) + __popc(a.w & c.w);
        }
        acc = __reduce_add_sync(0xffffffffu, acc);
        if ((tid & 31) == 0) red[tid >> 5] = (float)acc;
        __syncthreads();
        if (tid == 0) {
            float inter = red[0] + red[1] + red[2] + red[3] +
                          red[4] + red[5] + red[6] + red[7];
            float uni = fmaxf((float)(g_area[b][i] + g_area[b][j]) - inter, 1.f);
            if (inter / uni >= IOU_T) atomicOr(&g_conf[b][j][i >> 5], 1u << (i & 31));
        }
        __syncthreads();
    }
    __shared__ int is_last;
    if (tid == 0) {
        __threadfence();
        is_last = (atomicAdd(&g_done[b], 1) == PGRID - 1) ? 1 : 0;
    }
    __syncthreads();
    if (!is_last) return;
    __threadfence();
    __shared__ unsigned conf[NQ][4];
    __shared__ float ssc[NQ];
    __shared__ unsigned keptm[4];
    __shared__ int s_count;
    if (tid < NQ) {
        conf[tid][0] = g_conf[b][tid][0];
        conf[tid][1] = g_conf[b][tid][1];
        conf[tid][2] = g_conf[b][tid][2];
        conf[tid][3] = g_conf[b][tid][3];
        ssc[tid] = g_ss[b][tid];
    }
    __syncthreads();
    if (tid == 0) {
        unsigned k0 = 0, k1 = 0, k2 = 0, k3 = 0;
        int count = 0;
        bool stopped = false;
        for (int i = 0; i < NQ; i++) {
            if (ssc[i] < SCORE_T) stopped = true;
            unsigned c = (k0 & conf[i][0]) | (k1 & conf[i][1]) |
                         (k2 & conf[i][2]) | (k3 & conf[i][3]);
            bool take = !stopped && (c == 0u);
            if (take) {
                unsigned bit = 1u << (i & 31);
                if (i < 32) k0 |= bit; else if (i < 64) k1 |= bit;
                else if (i < 96) k2 |= bit; else k3 |= bit;
                count++;
                if (count >= TOPK) stopped = true;
            }
        }
        keptm[0] = k0; keptm[1] = k1; keptm[2] = k2; keptm[3] = k3;
        s_count = count;
        g_count[b] = count;
    }
    __syncthreads();
    if (tid < NQ) {
        int w = tid >> 5, bb = tid & 31;
        bool kept = (keptm[w] >> bb) & 1u;
        int below = __popc(keptm[w] & ((bb == 0) ? 0u : ((1u << bb) - 1u)));
        for (int ww = 0; ww < w; ww++) below += __popc(keptm[ww]);
        int dst = kept ? below : (s_count + (tid - below));
        g_src[b][dst] = g_order[b][tid];
        g_fs[b][dst] = ssc[tid];
        g_fl[b][dst] = g_sl[b][tid];
        int hb = g_need[b][tid] ? 1 : 0;
        g_hasbb[b][dst] = hb;
        if (hb) {
            g_x1[b][dst] = g_sx1[b][tid];
            g_x2[b][dst] = g_sx2[b][tid];
            g_y1[b][dst] = g_sy1[b][tid];
            g_y2[b][dst] = g_sy2[b][tid];
        }
    }
}

// ---------------- launch 4: rows 0..39 logits + bbox + W-downsample (8-row slabs)
__global__ void k_main40(const float* __restrict__ masks, float* __restrict__ outM) {
    int b = blockIdx.z, q = blockIdx.y;
    int h0 = blockIdx.x * MSLAB;
    int tid = threadIdx.x;
    float4* o4 = (float4*)(outM + ((size_t)(b * NQ + q) * HH + h0) * WW);
    if (q >= g_count[b]) {
        float4 v = make_float4(-20.f, -20.f, -20.f, -20.f);
#pragma unroll
        for (int i = 0; i < 5; i++)
            __stcs(&o4[i * 256 + tid], v);
        return;
    }
    int src = g_src[b][q];
    const float4* m4 = (const float4*)(masks + ((size_t)(b * NQ + src) * HH + h0) * WW);
    __shared__ float srow[MSLAB * SROWP];      // padded rows: 8 zero | 640 | 8 zero (21KB)
    __shared__ int rmn[8], rmx[8], rmy0[8], rmy1[8];
    int warp = tid >> 5, lane = tid & 31;
    if (tid < MSLAB * 16) {
        int r = tid >> 4, e = tid & 15;
        srow[r * SROWP + (e < 8 ? e : 640 + e)] = 0.f;
    }
    bool dobb = !g_hasbb[b][q];
    if (dobb) {
        int mnx = WW, mxx = -1, mny = 1 << 29, mxy = -1;
#pragma unroll
        for (int i = 0; i < 5; i++) {
            int idx = i * 256 + tid;
            int r = idx / 160, c = idx - r * 160;
            float4 m = __ldcs(&m4[idx]);
            float p0 = __saturatef(m.x), p1 = __saturatef(m.y);
            float p2 = __saturatef(m.z), p3 = __saturatef(m.w);
            *(float4*)&srow[r * SROWP + 8 + 4 * c] = make_float4(p0, p1, p2, p3);
            float4 o;
            o.x = logitf_(p0); o.y = logitf_(p1); o.z = logitf_(p2); o.w = logitf_(p3);
            __stcs(&o4[idx], o);
            bool a0 = m.x > MASK_T, a1 = m.y > MASK_T, a2 = m.z > MASK_T, a3 = m.w > MASK_T;
            if (a0 | a1 | a2 | a3) {
                int xb = 4 * c;
                int x0 = xb + (a0 ? 0 : (a1 ? 1 : (a2 ? 2 : 3)));
                int x1 = xb + (a3 ? 3 : (a2 ? 2 : (a1 ? 1 : 0)));
                mnx = min(mnx, x0); mxx = max(mxx, x1);
                mny = min(mny, r);  mxy = max(mxy, r);
            }
        }
        mnx = __reduce_min_sync(0xffffffffu, mnx);
        mxx = __reduce_max_sync(0xffffffffu, mxx);
        mny = __reduce_min_sync(0xffffffffu, mny);
        mxy = __reduce_max_sync(0xffffffffu, mxy);
        if (lane == 0) { rmn[warp] = mnx; rmx[warp] = mxx; rmy0[warp] = mny; rmy1[warp] = mxy; }
    } else {
#pragma unroll
        for (int i = 0; i < 5; i++) {
            int idx = i * 256 + tid;
            int r = idx / 160, c = idx - r * 160;
            float4 m = __ldcs(&m4[idx]);
            float p0 = __saturatef(m.x), p1 = __saturatef(m.y);
            float p2 = __saturatef(m.z), p3 = __saturatef(m.w);
            *(float4*)&srow[r * SROWP + 8 + 4 * c] = make_float4(p0, p1, p2, p3);
            float4 o;
            o.x = logitf_(p0); o.y = logitf_(p1); o.z = logitf_(p2); o.w = logitf_(p3);
            __stcs(&o4[idx], o);
        }
    }
    __syncthreads();
    if (dobb && tid == 0) {
        int a = rmn[0], c = rmx[0], y0 = rmy0[0], y1 = rmy1[0];
        for (int w = 1; w < 8; w++) {
            a = min(a, rmn[w]); c = max(c, rmx[w]);
            y0 = min(y0, rmy0[w]); y1 = max(y1, rmy1[w]);
        }
        if (c >= 0) {
            atomicMin(&g_x1[b][q], a);
            atomicMax(&g_x2[b][q], c);
            atomicMin(&g_y1[b][q], h0 + y0);
            atomicMax(&g_y2[b][q], h0 + y1);
        }
    }
    int half = lane >> 4, hl = lane & 15;
    float w0 = 1.f - fabsf((float)hl - 15.5f) * 0.0625f;
    float w1 = 1.f - ((float)hl + 0.5f) * 0.0625f;
    for (int pr = warp; pr < (MSLAB * FW) / 2; pr += 8) {
        int o = pr * 2 + half;
        int r = o / FW, wo = o - r * FW;
        const float* rp = srow + r * SROWP + 16 * wo;
        float acc = rp[hl] * w0 + rp[hl + 16] * w1;
        acc += __shfl_xor_sync(0xffffffffu, acc, 8);
        acc += __shfl_xor_sync(0xffffffffu, acc, 4);
        acc += __shfl_xor_sync(0xffffffffu, acc, 2);
        acc += __shfl_xor_sync(0xffffffffu, acc, 1);
        if (hl == 0)
            g_tmp[b][q][h0 + r][wo] = acc * g_invn[wo];
    }
}

// ---------------- launch 5: H-downsample -----------------------------------------
__global__ void k_redH() {
    int b = blockIdx.z, q = blockIdx.y, ho = blockIdx.x;
    if (q >= g_count[b]) return;
    int wo = threadIdx.x;
    if (wo >= FW) return;
    float c = 16.f * ho + 7.5f;
    int lo = max(0, 16 * ho - 8), hi = min(HH - 1, 16 * ho + 23);
    float acc = 0.f;
#pragma unroll 8
    for (int h = lo; h <= hi; h++)
        acc += (1.f - fabsf((float)h - c) * 0.0625f) * g_tmp[b][q][h][wo];
    g_ms[b][q][ho * FW + wo] = acc * g_invn[ho];
}

// ---------------- launch 6: pooled = mask_small @ feat^T (coalesced smem-tiled) --
__global__ void k_pool(const float* __restrict__ feat) {
    int b = blockIdx.z;
    int q0 = blockIdx.y * 10;
    int hw0 = blockIdx.x * 320;
    int count = g_count[b];
    int tid = threadIdx.x;
    int warp = tid >> 5, lane = tid & 31;
    __shared__ float ms[10][320];
    __shared__ float ft[DD][PKCH + 1];
    for (int i = tid; i < 3200; i += 384) {
        int qq = i / 320, k = i - qq * 320;
        int q = q0 + qq;
        ms[qq][k] = (q < count) ? g_ms[b][q][hw0 + k] : 0.f;
    }
    float acc[10];
#pragma unroll
    for (int i = 0; i < 10; i++) acc[i] = 0.f;
    const float* fb = feat + (size_t)b * DD * FHW + hw0;
    int rbase = warp * 32 + (lane >> 4);
    int kk = lane & 15;
    for (int k0 = 0; k0 < 320; k0 += PKCH) {
        __syncthreads();
#pragma unroll
        for (int rr = 0; rr < 16; rr++) {
            int d = rbase + rr * 2;
            ft[d][kk] = __ldg(&fb[(size_t)d * FHW + k0 + kk]);
        }
        __syncthreads();
#pragma unroll
        for (int k = 0; k < PKCH; k++) {
            float fv = ft[tid][k];
#pragma unroll
            for (int qq = 0; qq < 10; qq++) acc[qq] += ms[qq][k0 + k] * fv;
        }
    }
#pragma unroll
    for (int qq = 0; qq < 10; qq++)
        if (q0 + qq < count) atomicAdd(&g_pool[b][q0 + qq][tid], acc[qq]);
}

// ---------------- launch 7: finalize ---------------------------------------------
__global__ void k_final(float* __restrict__ outCls, float* __restrict__ outBox,
                        float* __restrict__ outEmb, int C1, int Cm1) {
    int b = blockIdx.y, q = blockIdx.x, tid = threadIdx.x;
    int count = g_count[b];
    bool valid = q < count;
    int label = min(max(g_fl[b][q], 0), Cm1);
    float slog = logitf_(fminf(fmaxf(g_fs[b][q], 0.f), 1.f));
    for (int c = tid; c < C1; c += blockDim.x) {
        float v = -10.f;
        if (valid) {
            if (c == C1 - 1) v = 0.f;
            if (c == label) v = slog;
        }
        outCls[(size_t)(b * NQ + q) * C1 + c] = v;
    }
    if (tid == 0) {
        float b0 = 0.f, b1 = 0.f, b2 = 0.f, b3 = 0.f;
        if (valid && g_y2[b][q] >= 0) {
            float x1 = (float)g_x1[b][q], x2 = (float)g_x2[b][q];
            float y1 = (float)g_y1[b][q], y2 = (float)g_y2[b][q];
            b0 = fminf(fmaxf((x1 + x2) * 0.5f / (float)WW, 0.f), 1.f);
            b1 = fminf(fmaxf((y1 + y2) * 0.5f / (float)HH, 0.f), 1.f);
            b2 = fminf(fmaxf(fmaxf(x2 - x1, 0.f) / (float)WW, 0.f), 1.f);
            b3 = fminf(fmaxf(fmaxf(y2 - y1, 0.f) / (float)HH, 0.f), 1.f);
        }
        float4* bp = (float4*)(outBox + (size_t)(b * NQ + q) * 4);
        *bp = make_float4(b0, b1, b2, b3);
    }
    __shared__ float sh[12];
    __shared__ float s_den, s_nrm;
    float part = 0.f;
    if (valid)
        for (int i = tid; i < FHW; i += blockDim.x) part += g_ms[b][q][i];
    for (int o = 16; o > 0; o >>= 1) part += __shfl_down_sync(0xffffffffu, part, o);
    if ((tid & 31) == 0) sh[tid >> 5] = part;
    __syncthreads();
    if (tid == 0) {
        float s = 0.f;
        for (int i = 0; i < 12; i++) s += sh[i];
        s_den = fmaxf(s, 1e-6f);
    }
    __syncthreads();
    float v = valid ? g_pool[b][q][tid] / s_den : 0.f;
    float p2 = v * v;
    for (int o = 16; o > 0; o >>= 1) p2 += __shfl_down_sync(0xffffffffu, p2, o);
    if ((tid & 31) == 0) sh[tid >> 5] = p2;
    __syncthreads();
    if (tid == 0) {
        float s = 0.f;
        for (int i = 0; i < 12; i++) s += sh[i];
        s_nrm = fmaxf(sqrtf(s), 1e-12f);
    }
    __syncthreads();
    outEmb[(size_t)(b * NQ + q) * DD + tid] = valid ? v / s_nrm : 0.f;
}

// ---------------- launch ----------------------------------------------------------
extern "C" void kernel_launch(void* const* d_in, const int* in_sizes, int n_in,
                              void* d_out, int out_size) {
    const float* masks  = (const float*)d_in[0];
    const int*   labels = (const int*)d_in[1];
    const float* scores = (const float*)d_in[2];
    const float* feat   = (const float*)d_in[3];
    float* out = (float*)d_out;

    int B = in_sizes[2] / NQ;
    if (B < 1) B = 1;
    if (B > MAXB) B = MAXB;
    long long fixed = (long long)B * NQ * HWPX + (long long)B * NQ * 4 + (long long)B * NQ * DD;
    int C1 = (int)(((long long)out_size - fixed) / ((long long)B * NQ));
    if (C1 < 2) C1 = 81;

    size_t off1 = (size_t)B * NQ * HWPX;
    size_t off2 = off1 + (size_t)B * NQ * C1;
    size_t off3 = off2 + (size_t)B * NQ * 4;

    k_sortinit<<<B, 128>>>(scores, labels);                 // #1
    k_packfill<<<dim3(40, NQ + 60, B), 256>>>(masks, out);  // #2 (fused fill+pack)
    k_iou<<<dim3(PGRID, B), 256>>>();                       // #3 (greedy in last block)
    k_main40<<<dim3(HH / MSLAB, TOPK, B), 256>>>(masks, out);// #4 -> profiled
    k_redH<<<dim3(FH, TOPK, B), 64>>>();                    // #5
    k_pool<<<dim3(5, 4, B), 384>>>(feat);                   // #6
    k_final<<<dim3(NQ, B), 384>>>(out + off1, out + off2, out + off3, C1, C1 - 2); // #7
}

// round 16
// speedup vs baseline: 1.1979x; 1.0903x over previous
#include <cuda_runtime.h>

#define NQ 100
#define HH 640
#define WW 640
#define HWPX (HH*WW)
#define WORDS (HWPX/32)
#define VWORDS (WORDS/4)
#define FH 40
#define FW 40
#define FHW (FH*FW)
#define DD 384
#define MAXB 2
#define MAXPAIRS 4950
#define PGRID 128
#define SLAB 16
#define MSLAB 8
#define SROWP 656
#define PKCH 16
#define MASK_T 0.4f
#define SCORE_T 0.35f
#define IOU_T 0.85f
#define TOPK 40

// ---------------- scratch (device globals; no allocation allowed) ----------------
__device__ int      g_order[MAXB][NQ];
__device__ float    g_ss[MAXB][NQ];
__device__ int      g_sl[MAXB][NQ];
__device__ unsigned char g_need[MAXB][NQ];
__device__ unsigned short g_pairs[MAXB][MAXPAIRS];
__device__ int      g_npairs[MAXB];
__device__ unsigned g_bits[MAXB][NQ][WORDS];
__device__ int      g_area[MAXB][NQ];
__device__ unsigned g_conf[MAXB][NQ][4];
__device__ int      g_done[MAXB];
__device__ int      g_count[MAXB];
__device__ int      g_src[MAXB][NQ];
__device__ int      g_hasbb[MAXB][NQ];
__device__ float    g_fs[MAXB][NQ];
__device__ int      g_fl[MAXB][NQ];
__device__ int      g_sx1[MAXB][NQ], g_sx2[MAXB][NQ], g_sy1[MAXB][NQ], g_sy2[MAXB][NQ];
__device__ int      g_x1[MAXB][NQ], g_x2[MAXB][NQ], g_y1[MAXB][NQ], g_y2[MAXB][NQ];
__device__ float    g_tmp[MAXB][NQ][HH][FW];
__device__ float    g_ms[MAXB][NQ][FHW];
__device__ float    g_pool[MAXB][NQ][DD];
__device__ float    g_invn[FW];

__device__ __forceinline__ float logitf_(float p) {
    p = fminf(fmaxf(p, 1e-4f), 1.0f - 1e-4f);
    return 0.69314718056f * (__log2f(p) - __log2f(1.0f - p));
}

// ---------------- launch 1: sort + pair enumeration + all scratch init -----------
__global__ void k_sortinit(const float* __restrict__ scores, const int* __restrict__ labels) {
    int b = blockIdx.x, tid = threadIdx.x;
    __shared__ float s[NQ];
    __shared__ int l[NQ];
    __shared__ float ss_s[NQ];
    __shared__ int sl_s[NQ];
    __shared__ unsigned char need[NQ];
    __shared__ int np;
    if (tid < NQ) { s[tid] = scores[b * NQ + tid]; l[tid] = labels[b * NQ + tid]; need[tid] = 0; }
    if (tid == 0) { np = 0; g_done[b] = 0; }
    for (int i = tid; i < NQ * DD; i += 128) (&g_pool[b][0][0])[i] = 0.f;
    if (tid < NQ) {
        g_area[b][tid] = 0;
        g_x1[b][tid] = 1 << 29; g_x2[b][tid] = -1;
        g_y1[b][tid] = 1 << 29; g_y2[b][tid] = -1;
        g_sx1[b][tid] = 1 << 29; g_sx2[b][tid] = -1;
        g_sy1[b][tid] = 1 << 29; g_sy2[b][tid] = -1;
        g_conf[b][tid][0] = 0u; g_conf[b][tid][1] = 0u;
        g_conf[b][tid][2] = 0u; g_conf[b][tid][3] = 0u;
    }
    if (tid < FW) {
        float c = 16.f * tid + 7.5f;
        int lo = max(0, 16 * tid - 8), hi = min(WW - 1, 16 * tid + 23);
        float sum = 0.f;
        for (int j = lo; j <= hi; j++) sum += 1.f - fabsf((float)j - c) * 0.0625f;
        g_invn[tid] = 1.f / sum;
    }
    __syncthreads();
    if (tid < NQ) {
        float si = s[tid];
        int r = 0;
        for (int j = 0; j < NQ; j++)
            r += (s[j] > si) || (s[j] == si && j < tid);
        g_order[b][r] = tid;
        g_ss[b][r] = si;
        g_sl[b][r] = l[tid];
        ss_s[r] = si;
        sl_s[r] = l[tid];
    }
    __syncthreads();
    if (tid < NQ && ss_s[tid] >= SCORE_T) {
        int i = tid, li = sl_s[i];
        for (int j = i + 1; j < NQ; j++)
            if (sl_s[j] == li && ss_s[j] >= SCORE_T) {
                int p = atomicAdd(&np, 1);
                g_pairs[b][p] = (unsigned short)((i << 8) | j);
                need[i] = 1; need[j] = 1;
            }
    }
    __syncthreads();
    if (tid < NQ) g_need[b][tid] = need[tid];
    if (tid == 0) g_npairs[b] = np;
}

// ---------------- launch 2: fill rows 40..99 + bit-pack + area + bbox ------------
__global__ void k_packfill(const float* __restrict__ masks, float* __restrict__ outM) {
    int b = blockIdx.z, y = blockIdx.y, tid = threadIdx.x;
    if (y >= NQ) {
        int q = y - 60;                        // rows 40..99: always invalid
        int h0 = blockIdx.x * SLAB;
        float4* o4 = (float4*)(outM + ((size_t)(b * NQ + q) * HH + h0) * WW);
        float4 v = make_float4(-20.f, -20.f, -20.f, -20.f);
#pragma unroll
        for (int i = 0; i < 10; i++)
            __stcs(&o4[i * 256 + tid], v);
        return;
    }
    int q = y;
    if (!g_need[b][q]) return;
    int src = g_order[b][q];
    const float4* m4 = (const float4*)(masks + (size_t)(b * NQ + src) * HWPX);
    int warp = tid >> 5, lane = tid & 31;
    int wb = blockIdx.x * 320 + warp * 40;     // 40 blocks * 8 warps * 40 words
    int acc = 0;
    int mnx = WW, mxx = -1, mny = 1 << 29, mxy = -1;
#pragma unroll
    for (int i = 0; i < 10; i++) {
        int wd = wb + i * 4;
        int f = wd * 8 + lane;
        float4 m = __ldcs(&m4[f]);
        bool a0 = m.x > MASK_T, a1 = m.y > MASK_T, a2 = m.z > MASK_T, a3 = m.w > MASK_T;
        unsigned b0 = __ballot_sync(0xffffffffu, a0);
        unsigned b1 = __ballot_sync(0xffffffffu, a1);
        unsigned b2 = __ballot_sync(0xffffffffu, a2);
        unsigned b3 = __ballot_sync(0xffffffffu, a3);
        if (lane == 0) {
            *(uint4*)&g_bits[b][q][wd] = make_uint4(b0, b1, b2, b3);
            acc += __popc(b0) + __popc(b1) + __popc(b2) + __popc(b3);
        }
        if (a0 | a1 | a2 | a3) {
            int r = f / 160;
            int xb = 4 * (f - r * 160);
            int x0 = xb + (a0 ? 0 : (a1 ? 1 : (a2 ? 2 : 3)));
            int x1 = xb + (a3 ? 3 : (a2 ? 2 : (a1 ? 1 : 0)));
            mnx = min(mnx, x0); mxx = max(mxx, x1);
            mny = min(mny, r);  mxy = max(mxy, r);
        }
    }
    if (lane == 0) atomicAdd(&g_area[b][q], acc);
    mnx = __reduce_min_sync(0xffffffffu, mnx);
    mxx = __reduce_max_sync(0xffffffffu, mxx);
    mny = __reduce_min_sync(0xffffffffu, mny);
    mxy = __reduce_max_sync(0xffffffffu, mxy);
    if (lane == 0 && mxy >= 0) {
        atomicMin(&g_sx1[b][q], mnx);
        atomicMax(&g_sx2[b][q], mxx);
        atomicMin(&g_sy1[b][q], mny);
        atomicMax(&g_sy2[b][q], mxy);
    }
}

// ---------------- launch 3: wide-grid IoU; last block runs greedy + pack ---------
__global__ void k_iou() {
    int b = blockIdx.y, tid = threadIdx.x;
    int np = g_npairs[b];
    __shared__ float red[8];
    for (int p = blockIdx.x; p < np; p += PGRID) {
        int pr = g_pairs[b][p];
        int i = pr >> 8, j = pr & 255;
        const uint4* bi = (const uint4*)g_bits[b][i];
        const uint4* bj = (const uint4*)g_bits[b][j];
        int acc = 0;
        for (int wd = tid; wd < VWORDS; wd += 256) {
            uint4 a = bi[wd], c = bj[wd];
            acc += __popc(a.x & c.x) + __popc(a.y & c.y) +
                   __popc(a.z & c.z) + __popc(a.w & c.w);
        }
        acc = __reduce_add_sync(0xffffffffu, acc);
        if ((tid & 31) == 0) red[tid >> 5] = (float)acc;
        __syncthreads();
        if (tid == 0) {
            float inter = red[0] + red[1] + red[2] + red[3] +
                          red[4] + red[5] + red[6] + red[7];
            float uni = fmaxf((float)(g_area[b][i] + g_area[b][j]) - inter, 1.f);
            if (inter / uni >= IOU_T) atomicOr(&g_conf[b][j][i >> 5], 1u << (i & 31));
        }
        __syncthreads();
    }
    __shared__ int is_last;
    if (tid == 0) {
        __threadfence();
        is_last = (atomicAdd(&g_done[b], 1) == PGRID - 1) ? 1 : 0;
    }
    __syncthreads();
    if (!is_last) return;
    __threadfence();
    __shared__ unsigned conf[NQ][4];
    __shared__ float ssc[NQ];
    __shared__ unsigned keptm[4];
    __shared__ int s_count;
    if (tid < NQ) {
        conf[tid][0] = g_conf[b][tid][0];
        conf[tid][1] = g_conf[b][tid][1];
        conf[tid][2] = g_conf[b][tid][2];
        conf[tid][3] = g_conf[b][tid][3];
        ssc[tid] = g_ss[b][tid];
    }
    __syncthreads();
    if (tid == 0) {
        unsigned k0 = 0, k1 = 0, k2 = 0, k3 = 0;
        int count = 0;
        bool stopped = false;
        for (int i = 0; i < NQ; i++) {
            if (ssc[i] < SCORE_T) stopped = true;
            unsigned c = (k0 & conf[i][0]) | (k1 & conf[i][1]) |
                         (k2 & conf[i][2]) | (k3 & conf[i][3]);
            bool take = !stopped && (c == 0u);
            if (take) {
                unsigned bit = 1u << (i & 31);
                if (i < 32) k0 |= bit; else if (i < 64) k1 |= bit;
                else if (i < 96) k2 |= bit; else k3 |= bit;
                count++;
                if (count >= TOPK) stopped = true;
            }
        }
        keptm[0] = k0; keptm[1] = k1; keptm[2] = k2; keptm[3] = k3;
        s_count = count;
        g_count[b] = count;
    }
    __syncthreads();
    if (tid < NQ) {
        int w = tid >> 5, bb = tid & 31;
        bool kept = (keptm[w] >> bb) & 1u;
        int below = __popc(keptm[w] & ((bb == 0) ? 0u : ((1u << bb) - 1u)));
        for (int ww = 0; ww < w; ww++) below += __popc(keptm[ww]);
        int dst = kept ? below : (s_count + (tid - below));
        g_src[b][dst] = g_order[b][tid];
        g_fs[b][dst] = ssc[tid];
        g_fl[b][dst] = g_sl[b][tid];
        int hb = g_need[b][tid] ? 1 : 0;
        g_hasbb[b][dst] = hb;
        if (hb) {
            g_x1[b][dst] = g_sx1[b][tid];
            g_x2[b][dst] = g_sx2[b][tid];
            g_y1[b][dst] = g_sy1[b][tid];
            g_y2[b][dst] = g_sy2[b][tid];
        }
    }
}

// ---------------- launch 4: rows 0..39 logits + bbox + W-downsample (8-row slabs)
__global__ void k_main40(const float* __restrict__ masks, float* __restrict__ outM) {
    int b = blockIdx.z, q = blockIdx.y;
    int h0 = blockIdx.x * MSLAB;
    int tid = threadIdx.x;
    float4* o4 = (float4*)(outM + ((size_t)(b * NQ + q) * HH + h0) * WW);
    if (q >= g_count[b]) {
        float4 v = make_float4(-20.f, -20.f, -20.f, -20.f);
#pragma unroll
        for (int i = 0; i < 5; i++)
            __stcs(&o4[i * 256 + tid], v);
        return;
    }
    int src = g_src[b][q];
    const float4* m4 = (const float4*)(masks + ((size_t)(b * NQ + src) * HH + h0) * WW);
    __shared__ float srow[MSLAB * SROWP];      // padded rows: 8 zero | 640 | 8 zero (21KB)
    __shared__ int rmn[8], rmx[8], rmy0[8], rmy1[8];
    int warp = tid >> 5, lane = tid & 31;
    if (tid < MSLAB * 16) {
        int r = tid >> 4, e = tid & 15;
        srow[r * SROWP + (e < 8 ? e : 640 + e)] = 0.f;
    }
    bool dobb = !g_hasbb[b][q];
    if (dobb) {
        int mnx = WW, mxx = -1, mny = 1 << 29, mxy = -1;
#pragma unroll
        for (int i = 0; i < 5; i++) {
            int idx = i * 256 + tid;
            int r = idx / 160, c = idx - r * 160;
            float4 m = __ldcs(&m4[idx]);
            float p0 = __saturatef(m.x), p1 = __saturatef(m.y);
            float p2 = __saturatef(m.z), p3 = __saturatef(m.w);
            *(float4*)&srow[r * SROWP + 8 + 4 * c] = make_float4(p0, p1, p2, p3);
            float4 o;
            o.x = logitf_(p0); o.y = logitf_(p1); o.z = logitf_(p2); o.w = logitf_(p3);
            __stcs(&o4[idx], o);
            bool a0 = m.x > MASK_T, a1 = m.y > MASK_T, a2 = m.z > MASK_T, a3 = m.w > MASK_T;
            if (a0 | a1 | a2 | a3) {
                int xb = 4 * c;
                int x0 = xb + (a0 ? 0 : (a1 ? 1 : (a2 ? 2 : 3)));
                int x1 = xb + (a3 ? 3 : (a2 ? 2 : (a1 ? 1 : 0)));
                mnx = min(mnx, x0); mxx = max(mxx, x1);
                mny = min(mny, r);  mxy = max(mxy, r);
            }
        }
        mnx = __reduce_min_sync(0xffffffffu, mnx);
        mxx = __reduce_max_sync(0xffffffffu, mxx);
        mny = __reduce_min_sync(0xffffffffu, mny);
        mxy = __reduce_max_sync(0xffffffffu, mxy);
        if (lane == 0) { rmn[warp] = mnx; rmx[warp] = mxx; rmy0[warp] = mny; rmy1[warp] = mxy; }
    } else {
#pragma unroll
        for (int i = 0; i < 5; i++) {
            int idx = i * 256 + tid;
            int r = idx / 160, c = idx - r * 160;
            float4 m = __ldcs(&m4[idx]);
            float p0 = __saturatef(m.x), p1 = __saturatef(m.y);
            float p2 = __saturatef(m.z), p3 = __saturatef(m.w);
            *(float4*)&srow[r * SROWP + 8 + 4 * c] = make_float4(p0, p1, p2, p3);
            float4 o;
            o.x = logitf_(p0); o.y = logitf_(p1); o.z = logitf_(p2); o.w = logitf_(p3);
            __stcs(&o4[idx], o);
        }
    }
    __syncthreads();
    if (dobb && tid == 0) {
        int a = rmn[0], c = rmx[0], y0 = rmy0[0], y1 = rmy1[0];
        for (int w = 1; w < 8; w++) {
            a = min(a, rmn[w]); c = max(c, rmx[w]);
            y0 = min(y0, rmy0[w]); y1 = max(y1, rmy1[w]);
        }
        if (c >= 0) {
            atomicMin(&g_x1[b][q], a);
            atomicMax(&g_x2[b][q], c);
            atomicMin(&g_y1[b][q], h0 + y0);
            atomicMax(&g_y2[b][q], h0 + y1);
        }
    }
    // quarter-warp (8-lane) per output W-downsample: LDS.128 + 4 FFMA + 3 shuffles.
    // Output wo's 32 taps live at padded offsets [16*wo, 16*wo+31]; lane ql holds
    // the float4 at 16*wo + 4*ql (16B aligned, pad-zeroed at both edges).
    int quarter = lane >> 3, ql = lane & 7;
    float wv0, wv1, wv2, wv3;
    {
        float t = (float)(4 * ql) - 8.f;       // tap position relative to 16*wo
        wv0 = 1.f - fabsf(t - 7.5f) * 0.0625f;
        wv1 = 1.f - fabsf(t - 6.5f) * 0.0625f;
        wv2 = 1.f - fabsf(t - 5.5f) * 0.0625f;
        wv3 = 1.f - fabsf(t - 4.5f) * 0.0625f;
    }
#pragma unroll
    for (int it = 0; it < (MSLAB * FW) / 32; it++) {   // 10 rounds, 4 outputs/warp
        int o = it * 32 + warp * 4 + quarter;
        int r = o / FW, wo = o - r * FW;
        float4 v = *(const float4*)&srow[r * SROWP + 16 * wo + 4 * ql];
        float acc = v.x * wv0 + v.y * wv1 + v.z * wv2 + v.w * wv3;
        acc += __shfl_xor_sync(0xffffffffu, acc, 4);
        acc += __shfl_xor_sync(0xffffffffu, acc, 2);
        acc += __shfl_xor_sync(0xffffffffu, acc, 1);
        if (ql == 0)
            g_tmp[b][q][h0 + r][wo] = acc * g_invn[wo];
    }
}

// ---------------- launch 5: H-downsample -----------------------------------------
__global__ void k_redH() {
    int b = blockIdx.z, q = blockIdx.y, ho = blockIdx.x;
    if (q >= g_count[b]) return;
    int wo = threadIdx.x;
    if (wo >= FW) return;
    float c = 16.f * ho + 7.5f;
    int lo = max(0, 16 * ho - 8), hi = min(HH - 1, 16 * ho + 23);
    float acc = 0.f;
#pragma unroll 8
    for (int h = lo; h <= hi; h++)
        acc += (1.f - fabsf((float)h - c) * 0.0625f) * g_tmp[b][q][h][wo];
    g_ms[b][q][ho * FW + wo] = acc * g_invn[ho];
}

// ---------------- launch 6: pooled = mask_small @ feat^T (coalesced smem-tiled) --
__global__ void k_pool(const float* __restrict__ feat) {
    int b = blockIdx.z;
    int q0 = blockIdx.y * 10;
    int hw0 = blockIdx.x * 320;
    int count = g_count[b];
    int tid = threadIdx.x;
    int warp = tid >> 5, lane = tid & 31;
    __shared__ float ms[10][320];
    __shared__ float ft[DD][PKCH + 1];
    for (int i = tid; i < 3200; i += 384) {
        int qq = i / 320, k = i - qq * 320;
        int q = q0 + qq;
        ms[qq][k] = (q < count) ? g_ms[b][q][hw0 + k] : 0.f;
    }
    float acc[10];
#pragma unroll
    for (int i = 0; i < 10; i++) acc[i] = 0.f;
    const float* fb = feat + (size_t)b * DD * FHW + hw0;
    int rbase = warp * 32 + (lane >> 4);
    int kk = lane & 15;
    for (int k0 = 0; k0 < 320; k0 += PKCH) {
        __syncthreads();
#pragma unroll
        for (int rr = 0; rr < 16; rr++) {
            int d = rbase + rr * 2;
            ft[d][kk] = __ldg(&fb[(size_t)d * FHW + k0 + kk]);
        }
        __syncthreads();
#pragma unroll
        for (int k = 0; k < PKCH; k++) {
            float fv = ft[tid][k];
#pragma unroll
            for (int qq = 0; qq < 10; qq++) acc[qq] += ms[qq][k0 + k] * fv;
        }
    }
#pragma unroll
    for (int qq = 0; qq < 10; qq++)
        if (q0 + qq < count) atomicAdd(&g_pool[b][q0 + qq][tid], acc[qq]);
}

// ---------------- launch 7: finalize ---------------------------------------------
__global__ void k_final(float* __restrict__ outCls, float* __restrict__ outBox,
                        float* __restrict__ outEmb, int C1, int Cm1) {
    int b = blockIdx.y, q = blockIdx.x, tid = threadIdx.x;
    int count = g_count[b];
    bool valid = q < count;
    int label = min(max(g_fl[b][q], 0), Cm1);
    float slog = logitf_(fminf(fmaxf(g_fs[b][q], 0.f), 1.f));
    for (int c = tid; c < C1; c += blockDim.x) {
        float v = -10.f;
        if (valid) {
            if (c == C1 - 1) v = 0.f;
            if (c == label) v = slog;
        }
        outCls[(size_t)(b * NQ + q) * C1 + c] = v;
    }
    if (tid == 0) {
        float b0 = 0.f, b1 = 0.f, b2 = 0.f, b3 = 0.f;
        if (valid && g_y2[b][q] >= 0) {
            float x1 = (float)g_x1[b][q], x2 = (float)g_x2[b][q];
            float y1 = (float)g_y1[b][q], y2 = (float)g_y2[b][q];
            b0 = fminf(fmaxf((x1 + x2) * 0.5f / (float)WW, 0.f), 1.f);
            b1 = fminf(fmaxf((y1 + y2) * 0.5f / (float)HH, 0.f), 1.f);
            b2 = fminf(fmaxf(fmaxf(x2 - x1, 0.f) / (float)WW, 0.f), 1.f);
            b3 = fminf(fmaxf(fmaxf(y2 - y1, 0.f) / (float)HH, 0.f), 1.f);
        }
        float4* bp = (float4*)(outBox + (size_t)(b * NQ + q) * 4);
        *bp = make_float4(b0, b1, b2, b3);
    }
    __shared__ float sh[12];
    __shared__ float s_den, s_nrm;
    float part = 0.f;
    if (valid)
        for (int i = tid; i < FHW; i += blockDim.x) part += g_ms[b][q][i];
    for (int o = 16; o > 0; o >>= 1) part += __shfl_down_sync(0xffffffffu, part, o);
    if ((tid & 31) == 0) sh[tid >> 5] = part;
    __syncthreads();
    if (tid == 0) {
        float s = 0.f;
        for (int i = 0; i < 12; i++) s += sh[i];
        s_den = fmaxf(s, 1e-6f);
    }
    __syncthreads();
    float v = valid ? g_pool[b][q][tid] / s_den : 0.f;
    float p2 = v * v;
    for (int o = 16; o > 0; o >>= 1) p2 += __shfl_down_sync(0xffffffffu, p2, o);
    if ((tid & 31) == 0) sh[tid >> 5] = p2;
    __syncthreads();
    if (tid == 0) {
        float s = 0.f;
        for (int i = 0; i < 12; i++) s += sh[i];
        s_nrm = fmaxf(sqrtf(s), 1e-12f);
    }
    __syncthreads();
    outEmb[(size_t)(b * NQ + q) * DD + tid] = valid ? v / s_nrm : 0.f;
}

// ---------------- launch ----------------------------------------------------------
extern "C" void kernel_launch(void* const* d_in, const int* in_sizes, int n_in,
                              void* d_out, int out_size) {
    const float* masks  = (const float*)d_in[0];
    const int*   labels = (const int*)d_in[1];
    const float* scores = (const float*)d_in[2];
    const float* feat   = (const float*)d_in[3];
    float* out = (float*)d_out;

    int B = in_sizes[2] / NQ;
    if (B < 1) B = 1;
    if (B > MAXB) B = MAXB;
    long long fixed = (long long)B * NQ * HWPX + (long long)B * NQ * 4 + (long long)B * NQ * DD;
    int C1 = (int)(((long long)out_size - fixed) / ((long long)B * NQ));
    if (C1 < 2) C1 = 81;

    size_t off1 = (size_t)B * NQ * HWPX;
    size_t off2 = off1 + (size_t)B * NQ * C1;
    size_t off3 = off2 + (size_t)B * NQ * 4;

    k_sortinit<<<B, 128>>>(scores, labels);                 // #1
    k_packfill<<<dim3(40, NQ + 60, B), 256>>>(masks, out);  // #2 (fused fill+pack)
    k_iou<<<dim3(PGRID, B), 256>>>();                       // #3 (greedy in last block)
    k_main40<<<dim3(HH / MSLAB, TOPK, B), 256>>>(masks, out);// #4 -> profiled
    k_redH<<<dim3(FH, TOPK, B), 64>>>();                    // #5
    k_pool<<<dim3(5, 4, B), 384>>>(feat);                   // #6
    k_final<<<dim3(NQ, B), 384>>>(out + off1, out + off2, out + off3, C1, C1 - 2); // #7
}